// round 8
// baseline (speedup 1.0000x reference)
#include <cuda_runtime.h>

#define TT   1024
#define BB   16
#define CC   1024
#define HH   16
#define KW   7
#define PADL 6
#define MM   (TT * BB)       // 16384
#define NN   (HH * KW)       // 112
#define KD   1024

#define BM 128
#define BK 32
#define GEMM_BLOCKS (MM / BM)                       // 128
#define DENSE_BYTES ((size_t)BB * HH * TT * TT * 4) // 1 GiB

#define ASTR 130
#define BSTR 33

// softmaxed conv weights, [m = t*16+b][o = h*7+k]
__device__ float g_wsm[(size_t)MM * NN];

typedef unsigned long long ull;
__device__ __forceinline__ ull pk2(float lo, float hi) {
    ull r; asm("mov.b64 %0,{%1,%2};" : "=l"(r) : "f"(lo), "f"(hi)); return r;
}
__device__ __forceinline__ void upk2(ull v, float& lo, float& hi) {
    asm("mov.b64 {%0,%1},%2;" : "=f"(lo), "=f"(hi) : "l"(v));
}
__device__ __forceinline__ void fma2(ull& d, ull a, ull b) {
    asm("fma.rn.f32x2 %0,%1,%2,%3;" : "=l"(d) : "l"(a), "l"(b), "l"(d));
}

// ---------------------------------------------------------------------------
// GEMM  w = x @ W^T (16384 x 112 x 1024) + masked softmax over K=7 -> g_wsm
// ---------------------------------------------------------------------------
__global__ __launch_bounds__(256)
void k_gemm_softmax(const float* __restrict__ x,
                    const float* __restrict__ W)
{
    __shared__ __align__(16) float Asf[BK * ASTR];
    __shared__ __align__(16) ull   Bsd[NN * BSTR];

    const int tid   = threadIdx.x;
    const int tx    = tid & 15;
    const int ty    = tid >> 4;
    const int mBase = blockIdx.x * BM;

    const int kk  = tid & 31;
    const int ldr = tid >> 5;

    ull acc[7][4];
#pragma unroll
    for (int j = 0; j < 7; j++)
#pragma unroll
        for (int r = 0; r < 4; r++) acc[j][r] = 0ull;

    for (int k0 = 0; k0 < KD; k0 += BK) {
#pragma unroll
        for (int rr = 0; rr < 16; rr++) {
            int r = ldr + rr * 8;
            Asf[kk * ASTR + r] = x[(size_t)(mBase + r) * KD + k0 + kk];
        }
#pragma unroll
        for (int oo = 0; oo < 14; oo++) {
            int o = ldr + oo * 8;
            float w = W[(size_t)o * KD + k0 + kk];
            Bsd[o * BSTR + kk] = pk2(w, w);
        }
        __syncthreads();

#pragma unroll 4
        for (int p = 0; p < BK; p++) {
            const float* ap = &Asf[p * ASTR + 8 * ty];
            ull a0 = *(const ull*)(ap + 0);
            ull a1 = *(const ull*)(ap + 2);
            ull a2 = *(const ull*)(ap + 4);
            ull a3 = *(const ull*)(ap + 6);
#pragma unroll
            for (int j = 0; j < 7; j++) {
                ull bb = Bsd[(tx * 7 + j) * BSTR + p];
                fma2(acc[j][0], a0, bb);
                fma2(acc[j][1], a1, bb);
                fma2(acc[j][2], a2, bb);
                fma2(acc[j][3], a3, bb);
            }
        }
        __syncthreads();
    }

#pragma unroll
    for (int rp = 0; rp < 4; rp++) {
        float f0[7], f1[7];
#pragma unroll
        for (int j = 0; j < 7; j++) upk2(acc[j][rp], f0[j], f1[j]);

#pragma unroll
        for (int half = 0; half < 2; half++) {
            float* f = half ? f1 : f0;
            int m = mBase + ty * 8 + rp * 2 + half;
            int t = m >> 4;
            int kmin = PADL - t; if (kmin < 0) kmin = 0;

            float mx = -1e30f;
#pragma unroll
            for (int k = 0; k < 7; k++)
                if (k >= kmin && f[k] > mx) mx = f[k];

            float e[7], s = 0.f;
#pragma unroll
            for (int k = 0; k < 7; k++) {
                e[k] = (k >= kmin) ? __expf(f[k] - mx) : 0.f;
                s += e[k];
            }
            float inv = 1.f / s;
            float* gp = &g_wsm[(size_t)m * NN + tx * 7];
#pragma unroll
            for (int k = 0; k < 7; k++)
                gp[k] = e[k] * inv;
        }
    }
}

// ---------------------------------------------------------------------------
// k_out: four consecutive t per block; 10 gather loads feed 4 outputs.
//   out[t,b,:] = sum_k wsm[t,b,h,k] * x[clamp(t-6+k), b, :]
// (no dense access -> can run concurrently with the memset)
// ---------------------------------------------------------------------------
__global__ __launch_bounds__(256)
void k_out(const float* __restrict__ x,
           float* __restrict__ out)
{
    const int t0  = blockIdx.x * 4;
    const int b   = blockIdx.y;
    const int tid = threadIdx.x;

    __shared__ float sw[4 * NN];
    for (int e = tid; e < 4 * NN; e += 256) {
        int r = e / NN, idx = e - r * NN;
        sw[e] = g_wsm[(size_t)((t0 + r) * BB + b) * NN + idx];
    }
    __syncthreads();

    const int h = tid >> 4;
    const float4* x4 = (const float4*)x;

    float4 v[10];
#pragma unroll
    for (int k = 0; k < 10; k++) {
        int pos = t0 - PADL + k;
        if (pos < 0) pos = 0;               // weight is exactly 0 there
        v[k] = x4[((size_t)(pos * BB + b) << 8) + tid];
    }

    float4* out4 = (float4*)out;
#pragma unroll
    for (int r = 0; r < 4; r++) {
        const float* wr = &sw[r * NN + h * 7];
        float4 a = make_float4(0.f, 0.f, 0.f, 0.f);
#pragma unroll
        for (int k = 0; k < 7; k++) {
            float wk = wr[k];
            a.x += wk * v[r + k].x;
            a.y += wk * v[r + k].y;
            a.z += wk * v[r + k].z;
            a.w += wk * v[r + k].w;
        }
        out4[((size_t)((t0 + r) * BB + b) << 8) + tid] = a;
    }
}

// ---------------------------------------------------------------------------
// k_band: one element per thread. gt = m*112 + idx, coalesced g_wsm read,
// scattered single STG into the zeroed dense band.
// ---------------------------------------------------------------------------
__global__ __launch_bounds__(256)
void k_band(float* __restrict__ dense)
{
    int gt  = blockIdx.x * 256 + threadIdx.x;   // 0 .. MM*NN-1
    int m   = gt / NN;
    int idx = gt - m * NN;
    int t   = m >> 4;
    int b   = m & 15;
    int h   = idx / 7;
    int k   = idx - h * 7;
    int col = t - PADL + k;
    if (col >= 0)
        dense[((size_t)(b * HH + h) << 20) + ((size_t)t << 10) + col] = g_wsm[gt];
}

// ---------------------------------------------------------------------------
// Fork/join capture:
//   main : gemm -> e_gemm -> k_out
//   side : (wait fork) memset -> (wait e_gemm) k_band -> e_done
//   main waits e_done.
// ---------------------------------------------------------------------------
struct Ctx {
    cudaStream_t side;
    cudaEvent_t  fork, gemm_done, side_done;
    Ctx() {
        cudaStreamCreateWithFlags(&side, cudaStreamNonBlocking);
        cudaEventCreateWithFlags(&fork,      cudaEventDisableTiming);
        cudaEventCreateWithFlags(&gemm_done, cudaEventDisableTiming);
        cudaEventCreateWithFlags(&side_done, cudaEventDisableTiming);
    }
};

extern "C" void kernel_launch(void* const* d_in, const int* in_sizes, int n_in,
                              void* d_out, int out_size)
{
    static Ctx c;                              // host-side handles, created once

    const float* x = (const float*)d_in[0];   // (T, B, C) fp32
    const float* W = (const float*)d_in[1];   // (H*K, C)  fp32
    float* out   = (float*)d_out;
    float* dense = out + (size_t)MM * CC;

    // fork side stream off the main (capture) stream
    cudaEventRecord(c.fork, 0);
    cudaStreamWaitEvent(c.side, c.fork, 0);

    // side: zero the 1 GiB dense buffer
    cudaMemsetAsync(dense, 0, DENSE_BYTES, c.side);

    // main: GEMM + softmax, then out
    k_gemm_softmax<<<GEMM_BLOCKS, 256>>>(x, W);
    cudaEventRecord(c.gemm_done, 0);

    dim3 g2(TT / 4, BB);
    k_out<<<g2, 256>>>(x, out);

    // side: band scatter once memset AND gemm are done
    cudaStreamWaitEvent(c.side, c.gemm_done, 0);
    k_band<<<(MM * NN) / 256, 256, 0, c.side>>>(dense);
    cudaEventRecord(c.side_done, c.side);

    // join
    cudaStreamWaitEvent(0, c.side_done, 0);
}

// round 9
// speedup vs baseline: 1.3276x; 1.3276x over previous
#include <cuda_runtime.h>

#define TT   1024
#define BB   16
#define CC   1024
#define HH   16
#define KW   7
#define PADL 6
#define MM   (TT * BB)       // 16384
#define NN   (HH * KW)       // 112
#define KD   1024

#define BM 128
#define BK 32
#define NTILE (KD / BK)                             // 32
#define GEMM_BLOCKS (MM / BM)                       // 128
#define DENSE_BYTES ((size_t)BB * HH * TT * TT * 4) // 1 GiB

#define ASTR 130
#define BSTR 33

// softmaxed conv weights, [m = t*16+b][o = h*7+k]
__device__ float g_wsm[(size_t)MM * NN];

typedef unsigned long long ull;
__device__ __forceinline__ ull pk2(float lo, float hi) {
    ull r; asm("mov.b64 %0,{%1,%2};" : "=l"(r) : "f"(lo), "f"(hi)); return r;
}
__device__ __forceinline__ void upk2(ull v, float& lo, float& hi) {
    asm("mov.b64 {%0,%1},%2;" : "=f"(lo), "=f"(hi) : "l"(v));
}
__device__ __forceinline__ void fma2(ull& d, ull a, ull b) {
    asm("fma.rn.f32x2 %0,%1,%2,%3;" : "=l"(d) : "l"(a), "l"(b), "l"(d));
}

// ---------------------------------------------------------------------------
// GEMM  w = x @ W^T (16384 x 112 x 1024) + masked softmax over K=7 -> g_wsm
// Software-pipelined: next tile's LDGs issue before the current compute,
// STS after compute. Hides DRAM latency at 8 warps/SM.
// ---------------------------------------------------------------------------
__global__ __launch_bounds__(256)
void k_gemm_softmax(const float* __restrict__ x,
                    const float* __restrict__ W)
{
    __shared__ __align__(16) float Asf[BK * ASTR];   // 16640 B
    __shared__ __align__(16) ull   Bsd[NN * BSTR];   // 29568 B

    const int tid   = threadIdx.x;
    const int tx    = tid & 15;     // head
    const int ty    = tid >> 4;     // 8-row group
    const int mBase = blockIdx.x * BM;

    const int kk  = tid & 31;       // loader column
    const int ldr = tid >> 5;       // loader row phase 0..7

    const float* pa = x + (size_t)(mBase + ldr) * KD + kk;
    const float* pb = W + (size_t)ldr * KD + kk;

    ull acc[7][4];
#pragma unroll
    for (int j = 0; j < 7; j++)
#pragma unroll
        for (int r = 0; r < 4; r++) acc[j][r] = 0ull;

    float aReg[16], bReg[14];

    // prologue: load tile 0
#pragma unroll
    for (int rr = 0; rr < 16; rr++) aReg[rr] = pa[rr * 8 * KD];
#pragma unroll
    for (int oo = 0; oo < 14; oo++) bReg[oo] = pb[oo * 8 * KD];
#pragma unroll
    for (int rr = 0; rr < 16; rr++) Asf[kk * ASTR + ldr + rr * 8] = aReg[rr];
#pragma unroll
    for (int oo = 0; oo < 14; oo++) Bsd[(ldr + oo * 8) * BSTR + kk] = pk2(bReg[oo], bReg[oo]);
    __syncthreads();

    for (int kt = 1; kt <= NTILE; kt++) {
        const int k0 = kt * BK;
        if (kt < NTILE) {
            // issue next tile's LDGs now; they land during compute
#pragma unroll
            for (int rr = 0; rr < 16; rr++) aReg[rr] = pa[rr * 8 * KD + k0];
#pragma unroll
            for (int oo = 0; oo < 14; oo++) bReg[oo] = pb[oo * 8 * KD + k0];
        }

#pragma unroll 4
        for (int p = 0; p < BK; p++) {
            const float* ap = &Asf[p * ASTR + 8 * ty];
            ull a0 = *(const ull*)(ap + 0);
            ull a1 = *(const ull*)(ap + 2);
            ull a2 = *(const ull*)(ap + 4);
            ull a3 = *(const ull*)(ap + 6);
#pragma unroll
            for (int j = 0; j < 7; j++) {
                ull bb = Bsd[(tx * 7 + j) * BSTR + p];
                fma2(acc[j][0], a0, bb);
                fma2(acc[j][1], a1, bb);
                fma2(acc[j][2], a2, bb);
                fma2(acc[j][3], a3, bb);
            }
        }
        __syncthreads();

        if (kt < NTILE) {
#pragma unroll
            for (int rr = 0; rr < 16; rr++) Asf[kk * ASTR + ldr + rr * 8] = aReg[rr];
#pragma unroll
            for (int oo = 0; oo < 14; oo++) Bsd[(ldr + oo * 8) * BSTR + kk] = pk2(bReg[oo], bReg[oo]);
            __syncthreads();
        }
    }

    // masked softmax over K=7 for this thread's 8 rows, head tx
#pragma unroll
    for (int rp = 0; rp < 4; rp++) {
        float f0[7], f1[7];
#pragma unroll
        for (int j = 0; j < 7; j++) upk2(acc[j][rp], f0[j], f1[j]);

#pragma unroll
        for (int half = 0; half < 2; half++) {
            float* f = half ? f1 : f0;
            int m = mBase + ty * 8 + rp * 2 + half;
            int t = m >> 4;
            int kmin = PADL - t; if (kmin < 0) kmin = 0;

            float mx = -1e30f;
#pragma unroll
            for (int k = 0; k < 7; k++)
                if (k >= kmin && f[k] > mx) mx = f[k];

            float e[7], s = 0.f;
#pragma unroll
            for (int k = 0; k < 7; k++) {
                e[k] = (k >= kmin) ? __expf(f[k] - mx) : 0.f;
                s += e[k];
            }
            float inv = 1.f / s;
            float* gp = &g_wsm[(size_t)m * NN + tx * 7];
#pragma unroll
            for (int k = 0; k < 7; k++)
                gp[k] = e[k] * inv;
        }
    }
}

// ---------------------------------------------------------------------------
// k_out: EIGHT consecutive t per block; 14 gather loads feed 8 outputs.
//   out[t,b,:] = sum_k wsm[t,b,h,k] * x[clamp(t-6+k), b, :]
// ---------------------------------------------------------------------------
__global__ __launch_bounds__(256)
void k_out(const float* __restrict__ x,
           float* __restrict__ out)
{
    const int t0  = blockIdx.x * 8;
    const int b   = blockIdx.y;
    const int tid = threadIdx.x;

    __shared__ float sw[8 * NN];
    for (int e = tid; e < 8 * NN; e += 256) {
        int r = e / NN, idx = e - r * NN;
        sw[e] = g_wsm[(size_t)((t0 + r) * BB + b) * NN + idx];
    }
    __syncthreads();

    const int h = tid >> 4;
    const float4* x4 = (const float4*)x;

    float4 v[14];
#pragma unroll
    for (int k = 0; k < 14; k++) {
        int pos = t0 - PADL + k;
        if (pos < 0) pos = 0;               // weight is exactly 0 there
        v[k] = x4[((size_t)(pos * BB + b) << 8) + tid];
    }

    float4* out4 = (float4*)out;
#pragma unroll
    for (int r = 0; r < 8; r++) {
        const float* wr = &sw[r * NN + h * 7];
        float4 a = make_float4(0.f, 0.f, 0.f, 0.f);
#pragma unroll
        for (int k = 0; k < 7; k++) {
            float wk = wr[k];
            a.x += wk * v[r + k].x;
            a.y += wk * v[r + k].y;
            a.z += wk * v[r + k].z;
            a.w += wk * v[r + k].w;
        }
        out4[((size_t)((t0 + r) * BB + b) << 8) + tid] = a;
    }
}

// ---------------------------------------------------------------------------
// k_band: one element per thread; coalesced g_wsm read, one scattered STG.
// ---------------------------------------------------------------------------
__global__ __launch_bounds__(256)
void k_band(float* __restrict__ dense)
{
    int gt  = blockIdx.x * 256 + threadIdx.x;   // 0 .. MM*NN-1
    int m   = gt / NN;
    int idx = gt - m * NN;
    int t   = m >> 4;
    int b   = m & 15;
    int h   = idx / 7;
    int k   = idx - h * 7;
    int col = t - PADL + k;
    if (col >= 0)
        dense[((size_t)(b * HH + h) << 20) + ((size_t)t << 10) + col] = g_wsm[gt];
}

// ---------------------------------------------------------------------------
// Serial: gemm -> memset(dense) -> k_out -> k_band.
// gemm first so ncu (position 0) profiles it.
// ---------------------------------------------------------------------------
extern "C" void kernel_launch(void* const* d_in, const int* in_sizes, int n_in,
                              void* d_out, int out_size)
{
    const float* x = (const float*)d_in[0];   // (T, B, C) fp32
    const float* W = (const float*)d_in[1];   // (H*K, C)  fp32
    float* out   = (float*)d_out;
    float* dense = out + (size_t)MM * CC;

    k_gemm_softmax<<<GEMM_BLOCKS, 256>>>(x, W);
    cudaMemsetAsync(dense, 0, DENSE_BYTES);
    dim3 g2(TT / 8, BB);
    k_out<<<g2, 256>>>(x, out);
    k_band<<<(MM * NN) / 256, 256>>>(dense);
}